// round 2
// baseline (speedup 1.0000x reference)
#include <cuda_runtime.h>
#include <cuda_bf16.h>
#include <math.h>

#define TWO_PI_F 6.283185307179586f
#define EPS_F 1e-8f

// -------- device scratch (no allocation allowed) --------
__device__ float g_inv[64 * 64];
__device__ float g_det;
__device__ int   g_flag;   // 1 => Sigma is exactly identity (fast path)

// ============================================================
// Prep kernel: single block. Checks Sigma == I exactly.
// If not, Gauss-Jordan inverse with partial pivoting + det.
// ============================================================
__global__ void prep_kernel(const float* __restrict__ Sigma) {
    __shared__ float A[64][129];   // augmented [Sigma | I], padded stride
    __shared__ float fcol[64];
    __shared__ float s_det;
    __shared__ int   s_ident;
    __shared__ int   s_piv;

    const int tid = threadIdx.x;
    const int bd  = blockDim.x;

    if (tid == 0) { s_ident = 1; s_det = 1.0f; }
    __syncthreads();

    // exact identity check (vectorized: 4096 floats = 1024 float4)
    {
        const float4* S4 = reinterpret_cast<const float4*>(Sigma);
        for (int i = tid; i < 1024; i += bd) {
            float4 v = S4[i];
            int e0 = (i * 4 + 0), e1 = (i * 4 + 1), e2 = (i * 4 + 2), e3 = (i * 4 + 3);
            float x0 = ((e0 >> 6) == (e0 & 63)) ? 1.0f : 0.0f;
            float x1 = ((e1 >> 6) == (e1 & 63)) ? 1.0f : 0.0f;
            float x2 = ((e2 >> 6) == (e2 & 63)) ? 1.0f : 0.0f;
            float x3 = ((e3 >> 6) == (e3 & 63)) ? 1.0f : 0.0f;
            if (v.x != x0 || v.y != x1 || v.z != x2 || v.w != x3)
                atomicExch(&s_ident, 0);
        }
    }
    __syncthreads();

    if (s_ident) {
        if (tid == 0) { g_det = 1.0f; g_flag = 1; }
        return;
    }

    // build augmented matrix
    for (int i = tid; i < 64 * 64; i += bd) {
        int r = i >> 6, c = i & 63;
        A[r][c]      = Sigma[i];
        A[r][64 + c] = (r == c) ? 1.0f : 0.0f;
    }
    __syncthreads();

    for (int k = 0; k < 64; k++) {
        // partial pivot (single-thread scan; this path is cold)
        if (tid == 0) {
            int   p  = k;
            float mx = fabsf(A[k][k]);
            for (int i = k + 1; i < 64; i++) {
                float v = fabsf(A[i][k]);
                if (v > mx) { mx = v; p = i; }
            }
            s_piv = p;
        }
        __syncthreads();
        const int p = s_piv;
        if (p != k) {
            for (int c = tid; c < 128; c += bd) {
                float t = A[k][c]; A[k][c] = A[p][c]; A[p][c] = t;
            }
        }
        __syncthreads();
        const float piv = A[k][k];
        if (tid == 0) s_det *= (p != k) ? -piv : piv;
        const float rpiv = 1.0f / piv;
        for (int c = tid; c < 128; c += bd) A[k][c] *= rpiv;
        __syncthreads();
        // snapshot factors before elimination touches column k
        for (int r = tid; r < 64; r += bd) fcol[r] = A[r][k];
        __syncthreads();
        for (int idx = tid; idx < 64 * 128; idx += bd) {
            int r = idx >> 7, c = idx & 127;
            if (r != k) A[r][c] -= fcol[r] * A[k][c];
        }
        __syncthreads();
    }

    for (int i = tid; i < 64 * 64; i += bd) {
        int r = i >> 6, c = i & 63;
        g_inv[i] = A[r][64 + c];
    }
    if (tid == 0) { g_det = s_det; g_flag = 0; }
}

// ============================================================
// Fast path: Sigma == I  =>  q = ||x - mu||^2, det = 1.
// One warp handles 8 samples (2048 contiguous bytes = 128 float4):
//   lane l loads float4 #(l + 32*j), j = 0..3  (MLP = 4).
//   float4 f belongs to sample f/16, component (f%16)*4
//   => load j of lane l belongs to sample s0 + 2*j + (l>>4).
// 16-lane butterfly reduction over hl = l&15; lanes 0 and 16 write
// 4 outputs each.
// ============================================================
__global__ __launch_bounds__(256)
void nll_identity_kernel(const float* __restrict__ samples,
                         const float* __restrict__ Phi,
                         const float* __restrict__ mu,
                         float* __restrict__ out, int N) {
    if (g_flag == 0) return;

    const int warp = (blockIdx.x * blockDim.x + threadIdx.x) >> 5;
    const int lane = threadIdx.x & 31;
    const int s0   = warp * 8;
    if (s0 >= N) return;

    const float4* smp = reinterpret_cast<const float4*>(samples);
    const float4* mu4 = reinterpret_cast<const float4*>(mu);

    const int hl   = lane & 15;          // half-lane index 0..15
    const int base = s0 * 16;            // float4 index of chunk start

    // front-batch all 4 global loads (MLP_p1 = 4)
    float4 v0 = smp[base + lane];
    float4 v1 = smp[base + lane + 32];
    float4 v2 = smp[base + lane + 64];
    float4 v3 = smp[base + lane + 96];
    float4 m  = mu4[hl];

    float d;
    float a0, a1, a2, a3;
    d = v0.x - m.x; a0  = d * d;
    d = v0.y - m.y; a0 += d * d;
    d = v0.z - m.z; a0 += d * d;
    d = v0.w - m.w; a0 += d * d;

    d = v1.x - m.x; a1  = d * d;
    d = v1.y - m.y; a1 += d * d;
    d = v1.z - m.z; a1 += d * d;
    d = v1.w - m.w; a1 += d * d;

    d = v2.x - m.x; a2  = d * d;
    d = v2.y - m.y; a2 += d * d;
    d = v2.z - m.z; a2 += d * d;
    d = v2.w - m.w; a2 += d * d;

    d = v3.x - m.x; a3  = d * d;
    d = v3.y - m.y; a3 += d * d;
    d = v3.z - m.z; a3 += d * d;
    d = v3.w - m.w; a3 += d * d;

    #pragma unroll
    for (int off = 8; off >= 1; off >>= 1) {
        a0 += __shfl_xor_sync(0xffffffffu, a0, off);
        a1 += __shfl_xor_sync(0xffffffffu, a1, off);
        a2 += __shfl_xor_sync(0xffffffffu, a2, off);
        a3 += __shfl_xor_sync(0xffffffffu, a3, off);
    }

    if (hl == 0) {
        const float c  = Phi[0] * rsqrtf(TWO_PI_F);   // det == 1
        const int  sA  = s0 + (lane >> 4);            // lane0 -> s0, lane16 -> s0+1
        out[sA]     = -__logf(c * __expf(-0.5f * a0) + EPS_F);
        out[sA + 2] = -__logf(c * __expf(-0.5f * a1) + EPS_F);
        out[sA + 4] = -__logf(c * __expf(-0.5f * a2) + EPS_F);
        out[sA + 6] = -__logf(c * __expf(-0.5f * a3) + EPS_F);
    }
}

// ============================================================
// General fallback (cold; early-exits when flag==1).
// Grid-stride so the exit cost is only ~1k tiny blocks.
// ============================================================
__global__ __launch_bounds__(128)
void nll_general_kernel(const float* __restrict__ samples,
                        const float* __restrict__ Phi,
                        const float* __restrict__ mu,
                        float* __restrict__ out, int N) {
    if (g_flag == 1) return;

    __shared__ float M[64 * 64];
    for (int i = threadIdx.x; i < 64 * 64; i += blockDim.x) M[i] = g_inv[i];
    __syncthreads();

    const float det = g_det;
    const float c   = Phi[0] / sqrtf(TWO_PI_F * det);

    for (int n = blockIdx.x * blockDim.x + threadIdx.x; n < N;
         n += gridDim.x * blockDim.x) {
        float dv[64];
        #pragma unroll
        for (int i = 0; i < 64; i++) dv[i] = samples[n * 64 + i] - mu[i];
        float q = 0.0f;
        for (int r = 0; r < 64; r++) {
            float t = 0.0f;
            #pragma unroll
            for (int cc = 0; cc < 64; cc++) t += M[r * 64 + cc] * dv[cc];
            q += t * dv[r];
        }
        out[n] = -logf(c * expf(-0.5f * q) + EPS_F);
    }
}

extern "C" void kernel_launch(void* const* d_in, const int* in_sizes, int n_in,
                              void* d_out, int out_size) {
    const float* samples = (const float*)d_in[0];
    const float* Phi     = (const float*)d_in[1];
    const float* mu      = (const float*)d_in[2];
    const float* Sigma   = (const float*)d_in[3];
    float* out = (float*)d_out;

    const int N = out_size;  // number of samples

    prep_kernel<<<1, 256>>>(Sigma);

    // fast path: 8 samples per warp, 8 warps per block => 64 samples/block
    const int samples_per_block = 8 * 8;
    const int blocks = (N + samples_per_block - 1) / samples_per_block;
    nll_identity_kernel<<<blocks, 256>>>(samples, Phi, mu, out, N);

    // general fallback (early-exits on fast path)
    nll_general_kernel<<<1184, 128>>>(samples, Phi, mu, out, N);
}